// round 15
// baseline (speedup 1.0000x reference)
#include <cuda_runtime.h>
#include <cuda_fp16.h>

#define NB   2
#define C    64
#define H    128
#define WW   128
#define HW   (H*WW)
#define NH   4
#define DK   16
#define KS   5
#define K2   25

// Scratch (allocation-free rule: __device__ globals).
// qp/kp/vp stored as fp16, pixel-major: [n, h*w, c].
__device__ uint2 g_qp [NB*HW*16];
__device__ uint2 g_kp [NB*HW*16];
__device__ uint2 g_vp [NB*HW*16];

__device__ __forceinline__ float ex2f(float x) {
    float r;
    asm("ex2.approx.f32 %0, %1;" : "=f"(r) : "f"(x));
    return r;
}

__device__ __forceinline__ void mma16816(float d[4],
    unsigned a0, unsigned a1, unsigned a2, unsigned a3,
    unsigned b0, unsigned b1)
{
    asm volatile(
        "mma.sync.aligned.m16n8k16.row.col.f32.f16.f16.f32 "
        "{%0,%1,%2,%3}, {%4,%5,%6,%7}, {%8,%9}, {%0,%1,%2,%3};"
        : "+f"(d[0]), "+f"(d[1]), "+f"(d[2]), "+f"(d[3])
        : "r"(a0), "r"(a1), "r"(a2), "r"(a3), "r"(b0), "r"(b1));
}

// ---------------------------------------------------------------------------
// Kernel 1: three 1x1 convs via tensor cores (unchanged from round 12).
// ---------------------------------------------------------------------------
__global__ __launch_bounds__(256) void conv_in_kernel(
    const float* __restrict__ q,
    const float* __restrict__ k,
    const float* __restrict__ v,
    const float* __restrict__ Wq,
    const float* __restrict__ Wk,
    const float* __restrict__ Wv)
{
    __shared__ __half Xh[128*72];   // [pix][c], stride 72 halves
    __shared__ __half Wh[64*72];    // [out][c], stride 72 halves

    const int which = blockIdx.y;
    const float* src = (which == 0) ? q  : (which == 1) ? k  : v;
    const float* Wsrc= (which == 0) ? Wq : (which == 1) ? Wk : Wv;
    uint2*       dst = (which == 0) ? g_qp : (which == 1) ? g_kp : g_vp;

    const int b       = blockIdx.x / (HW/128);
    const int pixBase = (blockIdx.x % (HW/128)) * 128;
    const int tid     = threadIdx.x;

    {
        const int pixL = tid & 127;
        const int cg   = tid >> 7;          // 0 or 1
        #pragma unroll
        for (int g = 0; g < 8; g++) {
            int c = g*8 + cg*4;
            const float* s = src + (size_t)(b*C + c)*HW + pixBase + pixL;
            float x0 = __ldg(s);
            float x1 = __ldg(s + HW);
            float x2 = __ldg(s + 2*HW);
            float x3 = __ldg(s + 3*HW);
            *(__half2*)&Xh[pixL*72 + c]     = __floats2half2_rn(x0, x1);
            *(__half2*)&Xh[pixL*72 + c + 2] = __floats2half2_rn(x2, x3);
        }
    }
    for (int i = tid; i < 64*16; i += 256) {
        int out = i >> 4, c4 = (i & 15)*4;
        float4 w = __ldg((const float4*)(Wsrc + out*64 + c4));
        *(__half2*)&Wh[out*72 + c4]     = __floats2half2_rn(w.x, w.y);
        *(__half2*)&Wh[out*72 + c4 + 2] = __floats2half2_rn(w.z, w.w);
    }
    __syncthreads();

    const int warp = tid >> 5;
    const int lane = tid & 31;
    const int r  = lane >> 2;
    const int qd = lane & 3;

    float d[8][4];
    #pragma unroll
    for (int nt = 0; nt < 8; nt++)
        #pragma unroll
        for (int i = 0; i < 4; i++) d[nt][i] = 0.f;

    const int rowA = warp*16 + r;
    #pragma unroll
    for (int ks = 0; ks < 4; ks++) {
        const int k0 = ks*16 + qd*2;
        unsigned a0 = *(const unsigned*)&Xh[ rowA      *72 + k0];
        unsigned a1 = *(const unsigned*)&Xh[(rowA + 8) *72 + k0];
        unsigned a2 = *(const unsigned*)&Xh[ rowA      *72 + k0 + 8];
        unsigned a3 = *(const unsigned*)&Xh[(rowA + 8) *72 + k0 + 8];
        #pragma unroll
        for (int nt = 0; nt < 8; nt++) {
            const int n = nt*8 + r;
            unsigned b0 = *(const unsigned*)&Wh[n*72 + k0];
            unsigned b1 = *(const unsigned*)&Wh[n*72 + k0 + 8];
            mma16816(d[nt], a0, a1, a2, a3, b0, b1);
        }
    }

    unsigned* dstU = (unsigned*)dst;
    const int pixA = pixBase + warp*16 + r;
    const int pixB = pixA + 8;
    #pragma unroll
    for (int nt = 0; nt < 8; nt++) {
        const int cHalf = (nt*8 + qd*2) >> 1;
        __half2 hA = __floats2half2_rn(d[nt][0], d[nt][1]);
        __half2 hB = __floats2half2_rn(d[nt][2], d[nt][3]);
        dstU[(size_t)(b*HW + pixA)*32 + cHalf] = *reinterpret_cast<unsigned*>(&hA);
        dstU[(size_t)(b*HW + pixB)*32 + cHalf] = *reinterpret_cast<unsigned*>(&hB);
    }
}

// ---------------------------------------------------------------------------
// Kernel 2: flow-guided attention + fused final 1x1 conv.
// Four pixels/warp (quarter-warp per pixel, lane owns 8 channels, LDG.128
// gathers). Head reduction = 1 shfl. Pass B re-reads probabilities from sP
// (smem) instead of keeping p[25] live -> reg peak drops, 3 blocks/SM.
// Block: 256 threads = 8 warps = 32 pixels = 8x4 tile.
// Epilogue: 2 error-compensated m16n8k64 strips per warp -> fp32 out.
// ---------------------------------------------------------------------------
__global__ __launch_bounds__(256, 3) void attn_kernel(const float* __restrict__ flow,
                                                      const float* __restrict__ Wfc,
                                                      float* __restrict__ out,
                                                      float* __restrict__ attn_out)
{
    __shared__ float sP[32][NH][K2];
    __shared__ float sInv[32][NH];
    __shared__ __half Ah[32*72];    // mid hi [pix][c]
    __shared__ __half Al[32*72];    // mid lo
    __shared__ __half Wh[64*72];    // Wfc hi [out][c]
    __shared__ __half Wl[64*72];    // Wfc lo

    const int tid  = threadIdx.x;
    const int warp = tid >> 5;
    const int lane = tid & 31;
    const int sp   = lane >> 3;      // subpixel 0..3
    const int l    = lane & 7;       // channel group: channels 8l..8l+7

    // Tile: 8 wide x 4 tall. 16 x-tiles, 32 y-tiles, NB batches.
    const int bx = blockIdx.x & 15;
    const int by = (blockIdx.x >> 4) & 31;
    const int b  = blockIdx.x >> 9;
    const int x0 = bx * 8;
    const int y0 = by * 4;

    const int lp = warp*4 + sp;      // local pixel 0..31
    const int rx = lp & 7;
    const int ry = lp >> 3;
    const int x = x0 + rx;
    const int y = y0 + ry;
    const int pix = y*WW + x;

    // Stage Wfc hi/lo early (no dependency on attention work).
    {
        const int o   = tid >> 2;            // 0..63
        const int c16 = (tid & 3) * 16;
        #pragma unroll
        for (int g = 0; g < 4; g++) {
            float4 w = __ldg((const float4*)(Wfc + o*64 + c16 + g*4));
            __half2 hh0 = __floats2half2_rn(w.x, w.y);
            __half2 hh1 = __floats2half2_rn(w.z, w.w);
            float2 r0 = __half22float2(hh0);
            float2 r1 = __half22float2(hh1);
            *(__half2*)&Wh[o*72 + c16 + g*4]     = hh0;
            *(__half2*)&Wh[o*72 + c16 + g*4 + 2] = hh1;
            *(__half2*)&Wl[o*72 + c16 + g*4]     = __floats2half2_rn(w.x - r0.x, w.y - r0.y);
            *(__half2*)&Wl[o*72 + c16 + g*4 + 2] = __floats2half2_rn(w.z - r1.x, w.w - r1.y);
        }
    }

    const float fx = flow[(b*2 + 0)*HW + pix];
    const float fy = flow[(b*2 + 1)*HW + pix];

    const float axf = (float)x + fx;
    const float ayf = (float)y + fy;
    const float x0f = floorf(axf), y0f = floorf(ayf);
    const int ix_base = (int)x0f - 2;
    const int iy_base = (int)y0f - 2;
    const float wx1 = axf - x0f, wx0 = 1.f - wx1;
    const float wy1 = ayf - y0f, wy0 = 1.f - wy1;
    const float LOG2E = 1.4426950408889634f;
    const float wy0e = wy0 * LOG2E, wy1e = wy1 * LOG2E;

    const uint4* __restrict__ qp = (const uint4*)g_qp;
    const uint4* __restrict__ kp = (const uint4*)g_kp;
    const uint4* __restrict__ vp = (const uint4*)g_vp;

    // q: 8 channels per lane, pre-scaled by 0.25 (exact in fp16).
    uint4 qh = __ldg(&qp[(size_t)(b*HW + pix)*8 + l]);
    const __half2 sc = __float2half2_rn(0.25f);
    const __half2 q01 = __hmul2(*reinterpret_cast<__half2*>(&qh.x), sc);
    const __half2 q23 = __hmul2(*reinterpret_cast<__half2*>(&qh.y), sc);
    const __half2 q45 = __hmul2(*reinterpret_cast<__half2*>(&qh.z), sc);
    const __half2 q67 = __hmul2(*reinterpret_cast<__half2*>(&qh.w), sc);

    const size_t batchOff = (size_t)b*HW;

    const bool interior = (ix_base >= 0) & (ix_base <= WW-6) &
                          (iy_base >= 0) & (iy_base <= H-6);
    const bool fastPath = __all_sync(0xffffffffu, interior);

    const int head = l >> 1;

    // ---- Pass A: per-lane PARTIAL logits (8-channel dots, reduction deferred) ----
    {
        float p[25];
        float drow[2][6];

        if (fastPath) {
            const uint4* kbase = kp + (batchOff + (size_t)iy_base*WW + ix_base)*8 + l;
            #pragma unroll
            for (int dy = 0; dy < 6; dy++) {
                const int cur = dy & 1;
                const uint4* kr = kbase + dy*(WW*8);
                #pragma unroll
                for (int dx = 0; dx < 6; dx++) {
                    uint4 kh = __ldg(kr + dx*8);
                    __half2 t = __hfma2(q01, *reinterpret_cast<__half2*>(&kh.x),
                                __hfma2(q23, *reinterpret_cast<__half2*>(&kh.y),
                                __hfma2(q45, *reinterpret_cast<__half2*>(&kh.z),
                                __hmul2(q67, *reinterpret_cast<__half2*>(&kh.w)))));
                    float2 tf = __half22float2(t);
                    drow[cur][dx] = tf.x + tf.y;
                }
                if (dy > 0) {
                    const int prv = cur ^ 1;
                    #pragma unroll
                    for (int tx = 0; tx < 5; tx++)
                        p[(dy-1)*5 + tx] =
                              wy0e * fmaf(wx0, drow[prv][tx], wx1 * drow[prv][tx+1])
                            + wy1e * fmaf(wx0, drow[cur][tx], wx1 * drow[cur][tx+1]);
                }
            }
        } else {
            int   ixc[6];
            float okX[6];
            #pragma unroll
            for (int dx = 0; dx < 6; dx++) {
                int ix = ix_base + dx;
                okX[dx] = ((unsigned)ix < (unsigned)WW) ? 1.f : 0.f;
                ixc[dx] = min(max(ix, 0), WW-1);
            }
            #pragma unroll
            for (int dy = 0; dy < 6; dy++) {
                const int cur = dy & 1;
                int iy = iy_base + dy;
                float okY = ((unsigned)iy < (unsigned)H) ? 1.f : 0.f;
                int iyc = min(max(iy, 0), H-1);
                const size_t rowOff = batchOff + (size_t)iyc*WW;
                #pragma unroll
                for (int dx = 0; dx < 6; dx++) {
                    uint4 kh = __ldg(&kp[(rowOff + ixc[dx])*8 + l]);
                    __half2 t = __hfma2(q01, *reinterpret_cast<__half2*>(&kh.x),
                                __hfma2(q23, *reinterpret_cast<__half2*>(&kh.y),
                                __hfma2(q45, *reinterpret_cast<__half2*>(&kh.z),
                                __hmul2(q67, *reinterpret_cast<__half2*>(&kh.w)))));
                    float2 tf = __half22float2(t);
                    drow[cur][dx] = (tf.x + tf.y) * (okY * okX[dx]);
                }
                if (dy > 0) {
                    const int prv = cur ^ 1;
                    #pragma unroll
                    for (int tx = 0; tx < 5; tx++)
                        p[(dy-1)*5 + tx] =
                              wy0e * fmaf(wx0, drow[prv][tx], wx1 * drow[prv][tx+1])
                            + wy1e * fmaf(wx0, drow[cur][tx], wx1 * drow[cur][tx+1]);
                }
            }
        }

        // Deferred head reduction: lane pair (l, l^1) spans one head's 16 ch.
        #pragma unroll
        for (int t = 0; t < K2; t++)
            p[t] += __shfl_xor_sync(0xffffffffu, p[t], 1);

        // Softmax (log2 domain, no max-shift). Publish to smem; p dies here.
        float sum = 0.f;
        #pragma unroll
        for (int t = 0; t < K2; t++) { p[t] = ex2f(p[t]); sum += p[t]; }

        if ((lane & 1) == 0) {
            #pragma unroll
            for (int t = 0; t < K2; t++) sP[lp][head][t] = p[t];
            sInv[lp][head] = 1.f / sum;
        }
    }
    __syncwarp();

    const float inv = sInv[lp][head];
    const float* __restrict__ pRow = &sP[lp][head][0];

    // ---- Pass B: V accumulation; separable coefficients; probs from smem ----
    float a0 = 0.f, a1 = 0.f, a2 = 0.f, a3 = 0.f,
          a4 = 0.f, a5 = 0.f, a6 = 0.f, a7 = 0.f;
    float rprev[6], rcur[6];

    if (fastPath) {
        const uint4* vbase = vp + (batchOff + (size_t)iy_base*WW + ix_base)*8 + l;
        #pragma unroll
        for (int gy = 0; gy < 6; gy++) {
            if (gy < 5) {
                float pr0 = pRow[gy*5+0], pr1 = pRow[gy*5+1], pr2 = pRow[gy*5+2],
                      pr3 = pRow[gy*5+3], pr4 = pRow[gy*5+4];
                rcur[0] = wx0*pr0;
                rcur[1] = fmaf(wx0, pr1, wx1*pr0);
                rcur[2] = fmaf(wx0, pr2, wx1*pr1);
                rcur[3] = fmaf(wx0, pr3, wx1*pr2);
                rcur[4] = fmaf(wx0, pr4, wx1*pr3);
                rcur[5] = wx1*pr4;
            } else {
                #pragma unroll
                for (int gx = 0; gx < 6; gx++) rcur[gx] = 0.f;
            }
            const uint4* vr = vbase + gy*(WW*8);
            #pragma unroll
            for (int gx = 0; gx < 6; gx++) {
                float coef = wy0 * rcur[gx];
                if (gy > 0) coef = fmaf(wy1, rprev[gx], coef);
                uint4 vh = __ldg(vr + gx*8);
                float2 v01 = __half22float2(*reinterpret_cast<__half2*>(&vh.x));
                float2 v23 = __half22float2(*reinterpret_cast<__half2*>(&vh.y));
                float2 v45 = __half22float2(*reinterpret_cast<__half2*>(&vh.z));
                float2 v67 = __half22float2(*reinterpret_cast<__half2*>(&vh.w));
                a0 = fmaf(coef, v01.x, a0); a1 = fmaf(coef, v01.y, a1);
                a2 = fmaf(coef, v23.x, a2); a3 = fmaf(coef, v23.y, a3);
                a4 = fmaf(coef, v45.x, a4); a5 = fmaf(coef, v45.y, a5);
                a6 = fmaf(coef, v67.x, a6); a7 = fmaf(coef, v67.y, a7);
            }
            #pragma unroll
            for (int gx = 0; gx < 6; gx++) rprev[gx] = rcur[gx];
        }
    } else {
        int   ixc[6];
        float okX[6];
        #pragma unroll
        for (int dx = 0; dx < 6; dx++) {
            int ix = ix_base + dx;
            okX[dx] = ((unsigned)ix < (unsigned)WW) ? 1.f : 0.f;
            ixc[dx] = min(max(ix, 0), WW-1);
        }
        #pragma unroll
        for (int gy = 0; gy < 6; gy++) {
            if (gy < 5) {
                float pr0 = pRow[gy*5+0], pr1 = pRow[gy*5+1], pr2 = pRow[gy*5+2],
                      pr3 = pRow[gy*5+3], pr4 = pRow[gy*5+4];
                rcur[0] = wx0*pr0;
                rcur[1] = fmaf(wx0, pr1, wx1*pr0);
                rcur[2] = fmaf(wx0, pr2, wx1*pr1);
                rcur[3] = fmaf(wx0, pr3, wx1*pr2);
                rcur[4] = fmaf(wx0, pr4, wx1*pr3);
                rcur[5] = wx1*pr4;
            } else {
                #pragma unroll
                for (int gx = 0; gx < 6; gx++) rcur[gx] = 0.f;
            }
            int iy = iy_base + gy;
            float okY = ((unsigned)iy < (unsigned)H) ? 1.f : 0.f;
            int iyc = min(max(iy, 0), H-1);
            const size_t rowOff = batchOff + (size_t)iyc*WW;
            #pragma unroll
            for (int gx = 0; gx < 6; gx++) {
                float coef = wy0 * rcur[gx];
                if (gy > 0) coef = fmaf(wy1, rprev[gx], coef);
                coef *= okY * okX[gx];
                uint4 vh = __ldg(&vp[(rowOff + ixc[gx])*8 + l]);
                float2 v01 = __half22float2(*reinterpret_cast<__half2*>(&vh.x));
                float2 v23 = __half22float2(*reinterpret_cast<__half2*>(&vh.y));
                float2 v45 = __half22float2(*reinterpret_cast<__half2*>(&vh.z));
                float2 v67 = __half22float2(*reinterpret_cast<__half2*>(&vh.w));
                a0 = fmaf(coef, v01.x, a0); a1 = fmaf(coef, v01.y, a1);
                a2 = fmaf(coef, v23.x, a2); a3 = fmaf(coef, v23.y, a3);
                a4 = fmaf(coef, v45.x, a4); a5 = fmaf(coef, v45.y, a5);
                a6 = fmaf(coef, v67.x, a6); a7 = fmaf(coef, v67.y, a7);
            }
            #pragma unroll
            for (int gx = 0; gx < 6; gx++) rprev[gx] = rcur[gx];
        }
    }

    // Stage mid = acc*inv into smem as fp16 hi + lo residual (8 channels).
    {
        float m[8] = {a0*inv, a1*inv, a2*inv, a3*inv,
                      a4*inv, a5*inv, a6*inv, a7*inv};
        #pragma unroll
        for (int g = 0; g < 4; g++) {
            __half2 h = __floats2half2_rn(m[2*g], m[2*g+1]);
            float2 f = __half22float2(h);
            *(__half2*)&Ah[lp*72 + l*8 + 2*g] = h;
            *(__half2*)&Al[lp*72 + l*8 + 2*g] =
                __floats2half2_rn(m[2*g] - f.x, m[2*g+1] - f.y);
        }
    }

    __syncthreads();

    // ---- Fused 1x1 conv epilogue: 2 compensated m16n8k64 strips per warp ----
    {
        const int r_ = lane >> 2;
        const int qd = lane & 3;
        const int n  = warp*8 + r_;
        const int c0 = warp*8 + qd*2;
        const int xA = x0 + r_;
        #pragma unroll
        for (int s = 0; s < 2; s++) {
            float dfr[4] = {0.f, 0.f, 0.f, 0.f};
            const int rowA = s*16 + r_;
            #pragma unroll
            for (int ks = 0; ks < 4; ks++) {
                const int k0 = ks*16 + qd*2;
                unsigned ah0 = *(const unsigned*)&Ah[ rowA     *72 + k0];
                unsigned ah1 = *(const unsigned*)&Ah[(rowA + 8)*72 + k0];
                unsigned ah2 = *(const unsigned*)&Ah[ rowA     *72 + k0 + 8];
                unsigned ah3 = *(const unsigned*)&Ah[(rowA + 8)*72 + k0 + 8];
                unsigned al0 = *(const unsigned*)&Al[ rowA     *72 + k0];
                unsigned al1 = *(const unsigned*)&Al[(rowA + 8)*72 + k0];
                unsigned al2 = *(const unsigned*)&Al[ rowA     *72 + k0 + 8];
                unsigned al3 = *(const unsigned*)&Al[(rowA + 8)*72 + k0 + 8];
                unsigned bh0 = *(const unsigned*)&Wh[n*72 + k0];
                unsigned bh1 = *(const unsigned*)&Wh[n*72 + k0 + 8];
                unsigned bl0 = *(const unsigned*)&Wl[n*72 + k0];
                unsigned bl1 = *(const unsigned*)&Wl[n*72 + k0 + 8];
                mma16816(dfr, ah0, ah1, ah2, ah3, bh0, bh1);
                mma16816(dfr, al0, al1, al2, al3, bh0, bh1);
                mma16816(dfr, ah0, ah1, ah2, ah3, bl0, bl1);
            }
            out[(size_t)(b*C + c0    )*HW + (y0 + s*2    )*WW + xA] = dfr[0];
            out[(size_t)(b*C + c0 + 1)*HW + (y0 + s*2    )*WW + xA] = dfr[1];
            out[(size_t)(b*C + c0    )*HW + (y0 + s*2 + 1)*WW + xA] = dfr[2];
            out[(size_t)(b*C + c0 + 1)*HW + (y0 + s*2 + 1)*WW + xA] = dfr[3];
        }
    }

    // attn map [n, nh, k2, h, w]; 4*25*32 = 3200 values per block.
    for (int i = tid; i < NH*K2*32; i += 256) {
        int pi = i & 31;
        int ht = i >> 5;
        int hh = ht / K2, t = ht % K2;
        float val = sP[pi][hh][t] * sInv[pi][hh];
        int py = y0 + (pi >> 3);
        int px = x0 + (pi & 7);
        attn_out[((size_t)(b*NH + hh)*K2 + t)*HW + py*WW + px] = val;
    }
}

// ---------------------------------------------------------------------------
extern "C" void kernel_launch(void* const* d_in, const int* in_sizes, int n_in,
                              void* d_out, int out_size)
{
    const float* q    = (const float*)d_in[0];
    const float* k    = (const float*)d_in[1];
    const float* v    = (const float*)d_in[2];
    const float* flow = (const float*)d_in[3];
    const float* Wq   = (const float*)d_in[4];
    const float* Wk   = (const float*)d_in[5];
    const float* Wv   = (const float*)d_in[6];
    const float* Wfc  = (const float*)d_in[7];

    float* out  = (float*)d_out;              // [n, c, h, w]
    float* attn = out + NB*C*HW;              // [n, nh, k2, h, w]

    dim3 g1(NB*HW/128, 3);
    conv_in_kernel<<<g1, 256>>>(q, k, v, Wq, Wk, Wv);
    attn_kernel<<<NB*16*32, 256>>>(flow, Wfc, out, attn);   // 8x4 tiles, fused
}

// round 16
// speedup vs baseline: 1.1054x; 1.1054x over previous
#include <cuda_runtime.h>
#include <cuda_fp16.h>

#define NB   2
#define C    64
#define H    128
#define WW   128
#define HW   (H*WW)
#define NH   4
#define DK   16
#define KS   5
#define K2   25

// Scratch (allocation-free rule: __device__ globals).
// qp/kp/vp stored as fp16, pixel-major: [n, h*w, c].
__device__ uint2 g_qp [NB*HW*16];
__device__ uint2 g_kp [NB*HW*16];
__device__ uint2 g_vp [NB*HW*16];

__device__ __forceinline__ float ex2f(float x) {
    float r;
    asm("ex2.approx.f32 %0, %1;" : "=f"(r) : "f"(x));
    return r;
}

__device__ __forceinline__ void mma16816(float d[4],
    unsigned a0, unsigned a1, unsigned a2, unsigned a3,
    unsigned b0, unsigned b1)
{
    asm volatile(
        "mma.sync.aligned.m16n8k16.row.col.f32.f16.f16.f32 "
        "{%0,%1,%2,%3}, {%4,%5,%6,%7}, {%8,%9}, {%0,%1,%2,%3};"
        : "+f"(d[0]), "+f"(d[1]), "+f"(d[2]), "+f"(d[3])
        : "r"(a0), "r"(a1), "r"(a2), "r"(a3), "r"(b0), "r"(b1));
}

// ---------------------------------------------------------------------------
// Kernel 1: three 1x1 convs via tensor cores.
// NEW: output bounced through smem (reusing Xh) so global stores are
// fully-coalesced STG.128 instead of scattered STG.32 (16B segments).
// ---------------------------------------------------------------------------
__global__ __launch_bounds__(256) void conv_in_kernel(
    const float* __restrict__ q,
    const float* __restrict__ k,
    const float* __restrict__ v,
    const float* __restrict__ Wq,
    const float* __restrict__ Wk,
    const float* __restrict__ Wv)
{
    __shared__ __half Xh[128*72];   // [pix][c], stride 72 halves; reused for D
    __shared__ __half Wh[64*72];    // [out][c], stride 72 halves

    const int which = blockIdx.y;
    const float* src = (which == 0) ? q  : (which == 1) ? k  : v;
    const float* Wsrc= (which == 0) ? Wq : (which == 1) ? Wk : Wv;
    uint2*       dst = (which == 0) ? g_qp : (which == 1) ? g_kp : g_vp;

    const int b       = blockIdx.x / (HW/128);
    const int pixBase = (blockIdx.x % (HW/128)) * 128;
    const int tid     = threadIdx.x;

    {
        const int pixL = tid & 127;
        const int cg   = tid >> 7;          // 0 or 1
        #pragma unroll
        for (int g = 0; g < 8; g++) {
            int c = g*8 + cg*4;
            const float* s = src + (size_t)(b*C + c)*HW + pixBase + pixL;
            float x0 = __ldg(s);
            float x1 = __ldg(s + HW);
            float x2 = __ldg(s + 2*HW);
            float x3 = __ldg(s + 3*HW);
            *(__half2*)&Xh[pixL*72 + c]     = __floats2half2_rn(x0, x1);
            *(__half2*)&Xh[pixL*72 + c + 2] = __floats2half2_rn(x2, x3);
        }
    }
    for (int i = tid; i < 64*16; i += 256) {
        int out = i >> 4, c4 = (i & 15)*4;
        float4 w = __ldg((const float4*)(Wsrc + out*64 + c4));
        *(__half2*)&Wh[out*72 + c4]     = __floats2half2_rn(w.x, w.y);
        *(__half2*)&Wh[out*72 + c4 + 2] = __floats2half2_rn(w.z, w.w);
    }
    __syncthreads();

    const int warp = tid >> 5;
    const int lane = tid & 31;
    const int r  = lane >> 2;
    const int qd = lane & 3;

    float d[8][4];
    #pragma unroll
    for (int nt = 0; nt < 8; nt++)
        #pragma unroll
        for (int i = 0; i < 4; i++) d[nt][i] = 0.f;

    const int rowA = warp*16 + r;
    #pragma unroll
    for (int ks = 0; ks < 4; ks++) {
        const int k0 = ks*16 + qd*2;
        unsigned a0 = *(const unsigned*)&Xh[ rowA      *72 + k0];
        unsigned a1 = *(const unsigned*)&Xh[(rowA + 8) *72 + k0];
        unsigned a2 = *(const unsigned*)&Xh[ rowA      *72 + k0 + 8];
        unsigned a3 = *(const unsigned*)&Xh[(rowA + 8) *72 + k0 + 8];
        #pragma unroll
        for (int nt = 0; nt < 8; nt++) {
            const int n = nt*8 + r;
            unsigned b0 = *(const unsigned*)&Wh[n*72 + k0];
            unsigned b1 = *(const unsigned*)&Wh[n*72 + k0 + 8];
            mma16816(d[nt], a0, a1, a2, a3, b0, b1);
        }
    }

    // All fragment reads of Xh complete -> reuse Xh as fp16 D staging buffer.
    __syncthreads();
    #pragma unroll
    for (int nt = 0; nt < 8; nt++) {
        const int cHalf = nt*8 + qd*2;
        const int pixLa = warp*16 + r;
        // banks = 4r + qd per nt: conflict-free (same pattern as fragment reads)
        *(__half2*)&Xh[ pixLa     *72 + cHalf] = __floats2half2_rn(d[nt][0], d[nt][1]);
        *(__half2*)&Xh[(pixLa + 8)*72 + cHalf] = __floats2half2_rn(d[nt][2], d[nt][3]);
    }
    __syncthreads();

    // Coalesced copy to global: 128 pixels x 8 uint4 (128B record each).
    uint4* dst4 = (uint4*)dst;
    #pragma unroll
    for (int kk = 0; kk < 4; kk++) {
        int u = tid + kk*256;
        int pixL = u >> 3;
        int oct  = u & 7;
        uint4 val = *(const uint4*)&Xh[pixL*72 + oct*8];
        dst4[(size_t)(b*HW + pixBase + pixL)*8 + oct] = val;
    }
}

// ---------------------------------------------------------------------------
// Kernel 2: flow-guided attention + fused final 1x1 conv.
// Four pixels/warp (lane owns 8 channels, LDG.128 gathers). Head reduction =
// 1 shfl. Pass B re-reads probabilities from sP (smem).
// NEW: pass-B rows accumulated in fp16 (hfma2) and flushed to fp32 per grid
// row -> converts drop 144->24/thread, fma-slots halve.
// Block: 256 threads = 8 warps = 32 pixels = 8x4 tile.
// ---------------------------------------------------------------------------
__global__ __launch_bounds__(256, 3) void attn_kernel(const float* __restrict__ flow,
                                                      const float* __restrict__ Wfc,
                                                      float* __restrict__ out,
                                                      float* __restrict__ attn_out)
{
    __shared__ float sP[32][NH][K2];
    __shared__ float sInv[32][NH];
    __shared__ __half Ah[32*72];    // mid hi [pix][c]
    __shared__ __half Al[32*72];    // mid lo
    __shared__ __half Wh[64*72];    // Wfc hi [out][c]
    __shared__ __half Wl[64*72];    // Wfc lo

    const int tid  = threadIdx.x;
    const int warp = tid >> 5;
    const int lane = tid & 31;
    const int sp   = lane >> 3;      // subpixel 0..3
    const int l    = lane & 7;       // channel group: channels 8l..8l+7

    // Tile: 8 wide x 4 tall. 16 x-tiles, 32 y-tiles, NB batches.
    const int bx = blockIdx.x & 15;
    const int by = (blockIdx.x >> 4) & 31;
    const int b  = blockIdx.x >> 9;
    const int x0 = bx * 8;
    const int y0 = by * 4;

    const int lp = warp*4 + sp;      // local pixel 0..31
    const int rx = lp & 7;
    const int ry = lp >> 3;
    const int x = x0 + rx;
    const int y = y0 + ry;
    const int pix = y*WW + x;

    // Stage Wfc hi/lo early (no dependency on attention work).
    {
        const int o   = tid >> 2;            // 0..63
        const int c16 = (tid & 3) * 16;
        #pragma unroll
        for (int g = 0; g < 4; g++) {
            float4 w = __ldg((const float4*)(Wfc + o*64 + c16 + g*4));
            __half2 hh0 = __floats2half2_rn(w.x, w.y);
            __half2 hh1 = __floats2half2_rn(w.z, w.w);
            float2 r0 = __half22float2(hh0);
            float2 r1 = __half22float2(hh1);
            *(__half2*)&Wh[o*72 + c16 + g*4]     = hh0;
            *(__half2*)&Wh[o*72 + c16 + g*4 + 2] = hh1;
            *(__half2*)&Wl[o*72 + c16 + g*4]     = __floats2half2_rn(w.x - r0.x, w.y - r0.y);
            *(__half2*)&Wl[o*72 + c16 + g*4 + 2] = __floats2half2_rn(w.z - r1.x, w.w - r1.y);
        }
    }

    const float fx = flow[(b*2 + 0)*HW + pix];
    const float fy = flow[(b*2 + 1)*HW + pix];

    const float axf = (float)x + fx;
    const float ayf = (float)y + fy;
    const float x0f = floorf(axf), y0f = floorf(ayf);
    const int ix_base = (int)x0f - 2;
    const int iy_base = (int)y0f - 2;
    const float wx1 = axf - x0f, wx0 = 1.f - wx1;
    const float wy1 = ayf - y0f, wy0 = 1.f - wy1;
    const float LOG2E = 1.4426950408889634f;
    const float wy0e = wy0 * LOG2E, wy1e = wy1 * LOG2E;

    const uint4* __restrict__ qp = (const uint4*)g_qp;
    const uint4* __restrict__ kp = (const uint4*)g_kp;
    const uint4* __restrict__ vp = (const uint4*)g_vp;

    // q: 8 channels per lane, pre-scaled by 0.25 (exact in fp16).
    uint4 qh = __ldg(&qp[(size_t)(b*HW + pix)*8 + l]);
    const __half2 sc = __float2half2_rn(0.25f);
    const __half2 q01 = __hmul2(*reinterpret_cast<__half2*>(&qh.x), sc);
    const __half2 q23 = __hmul2(*reinterpret_cast<__half2*>(&qh.y), sc);
    const __half2 q45 = __hmul2(*reinterpret_cast<__half2*>(&qh.z), sc);
    const __half2 q67 = __hmul2(*reinterpret_cast<__half2*>(&qh.w), sc);

    const size_t batchOff = (size_t)b*HW;

    const bool interior = (ix_base >= 0) & (ix_base <= WW-6) &
                          (iy_base >= 0) & (iy_base <= H-6);
    const bool fastPath = __all_sync(0xffffffffu, interior);

    const int head = l >> 1;

    // ---- Pass A: per-lane PARTIAL logits (8-channel dots, reduction deferred) ----
    {
        float p[25];
        float drow[2][6];

        if (fastPath) {
            const uint4* kbase = kp + (batchOff + (size_t)iy_base*WW + ix_base)*8 + l;
            #pragma unroll
            for (int dy = 0; dy < 6; dy++) {
                const int cur = dy & 1;
                const uint4* kr = kbase + dy*(WW*8);
                #pragma unroll
                for (int dx = 0; dx < 6; dx++) {
                    uint4 kh = __ldg(kr + dx*8);
                    __half2 t = __hfma2(q01, *reinterpret_cast<__half2*>(&kh.x),
                                __hfma2(q23, *reinterpret_cast<__half2*>(&kh.y),
                                __hfma2(q45, *reinterpret_cast<__half2*>(&kh.z),
                                __hmul2(q67, *reinterpret_cast<__half2*>(&kh.w)))));
                    float2 tf = __half22float2(t);
                    drow[cur][dx] = tf.x + tf.y;
                }
                if (dy > 0) {
                    const int prv = cur ^ 1;
                    #pragma unroll
                    for (int tx = 0; tx < 5; tx++)
                        p[(dy-1)*5 + tx] =
                              wy0e * fmaf(wx0, drow[prv][tx], wx1 * drow[prv][tx+1])
                            + wy1e * fmaf(wx0, drow[cur][tx], wx1 * drow[cur][tx+1]);
                }
            }
        } else {
            int   ixc[6];
            float okX[6];
            #pragma unroll
            for (int dx = 0; dx < 6; dx++) {
                int ix = ix_base + dx;
                okX[dx] = ((unsigned)ix < (unsigned)WW) ? 1.f : 0.f;
                ixc[dx] = min(max(ix, 0), WW-1);
            }
            #pragma unroll
            for (int dy = 0; dy < 6; dy++) {
                const int cur = dy & 1;
                int iy = iy_base + dy;
                float okY = ((unsigned)iy < (unsigned)H) ? 1.f : 0.f;
                int iyc = min(max(iy, 0), H-1);
                const size_t rowOff = batchOff + (size_t)iyc*WW;
                #pragma unroll
                for (int dx = 0; dx < 6; dx++) {
                    uint4 kh = __ldg(&kp[(rowOff + ixc[dx])*8 + l]);
                    __half2 t = __hfma2(q01, *reinterpret_cast<__half2*>(&kh.x),
                                __hfma2(q23, *reinterpret_cast<__half2*>(&kh.y),
                                __hfma2(q45, *reinterpret_cast<__half2*>(&kh.z),
                                __hmul2(q67, *reinterpret_cast<__half2*>(&kh.w)))));
                    float2 tf = __half22float2(t);
                    drow[cur][dx] = (tf.x + tf.y) * (okY * okX[dx]);
                }
                if (dy > 0) {
                    const int prv = cur ^ 1;
                    #pragma unroll
                    for (int tx = 0; tx < 5; tx++)
                        p[(dy-1)*5 + tx] =
                              wy0e * fmaf(wx0, drow[prv][tx], wx1 * drow[prv][tx+1])
                            + wy1e * fmaf(wx0, drow[cur][tx], wx1 * drow[cur][tx+1]);
                }
            }
        }

        // Deferred head reduction: lane pair (l, l^1) spans one head's 16 ch.
        #pragma unroll
        for (int t = 0; t < K2; t++)
            p[t] += __shfl_xor_sync(0xffffffffu, p[t], 1);

        // Softmax (log2 domain, no max-shift). Publish to smem; p dies here.
        float sum = 0.f;
        #pragma unroll
        for (int t = 0; t < K2; t++) { p[t] = ex2f(p[t]); sum += p[t]; }

        if ((lane & 1) == 0) {
            #pragma unroll
            for (int t = 0; t < K2; t++) sP[lp][head][t] = p[t];
            sInv[lp][head] = 1.f / sum;
        }
    }
    __syncwarp();

    const float inv = sInv[lp][head];
    const float* __restrict__ pRow = &sP[lp][head][0];

    // ---- Pass B: V accumulation; fp16 row accumulators, fp32 row flush ----
    float a0 = 0.f, a1 = 0.f, a2 = 0.f, a3 = 0.f,
          a4 = 0.f, a5 = 0.f, a6 = 0.f, a7 = 0.f;
    float rprev[6], rcur[6];
    const __half2 hz = __float2half2_rn(0.f);

    if (fastPath) {
        const uint4* vbase = vp + (batchOff + (size_t)iy_base*WW + ix_base)*8 + l;
        #pragma unroll
        for (int gy = 0; gy < 6; gy++) {
            if (gy < 5) {
                float pr0 = pRow[gy*5+0], pr1 = pRow[gy*5+1], pr2 = pRow[gy*5+2],
                      pr3 = pRow[gy*5+3], pr4 = pRow[gy*5+4];
                rcur[0] = wx0*pr0;
                rcur[1] = fmaf(wx0, pr1, wx1*pr0);
                rcur[2] = fmaf(wx0, pr2, wx1*pr1);
                rcur[3] = fmaf(wx0, pr3, wx1*pr2);
                rcur[4] = fmaf(wx0, pr4, wx1*pr3);
                rcur[5] = wx1*pr4;
            } else {
                #pragma unroll
                for (int gx = 0; gx < 6; gx++) rcur[gx] = 0.f;
            }
            const uint4* vr = vbase + gy*(WW*8);
            __half2 rc0 = hz, rc1 = hz, rc2 = hz, rc3 = hz;
            #pragma unroll
            for (int gx = 0; gx < 6; gx++) {
                float coef = wy0 * rcur[gx];
                if (gy > 0) coef = fmaf(wy1, rprev[gx], coef);
                __half2 c2 = __float2half2_rn(coef);
                uint4 vh = __ldg(vr + gx*8);
                rc0 = __hfma2(c2, *reinterpret_cast<__half2*>(&vh.x), rc0);
                rc1 = __hfma2(c2, *reinterpret_cast<__half2*>(&vh.y), rc1);
                rc2 = __hfma2(c2, *reinterpret_cast<__half2*>(&vh.z), rc2);
                rc3 = __hfma2(c2, *reinterpret_cast<__half2*>(&vh.w), rc3);
            }
            float2 f;
            f = __half22float2(rc0); a0 += f.x; a1 += f.y;
            f = __half22float2(rc1); a2 += f.x; a3 += f.y;
            f = __half22float2(rc2); a4 += f.x; a5 += f.y;
            f = __half22float2(rc3); a6 += f.x; a7 += f.y;
            #pragma unroll
            for (int gx = 0; gx < 6; gx++) rprev[gx] = rcur[gx];
        }
    } else {
        int   ixc[6];
        float okX[6];
        #pragma unroll
        for (int dx = 0; dx < 6; dx++) {
            int ix = ix_base + dx;
            okX[dx] = ((unsigned)ix < (unsigned)WW) ? 1.f : 0.f;
            ixc[dx] = min(max(ix, 0), WW-1);
        }
        #pragma unroll
        for (int gy = 0; gy < 6; gy++) {
            if (gy < 5) {
                float pr0 = pRow[gy*5+0], pr1 = pRow[gy*5+1], pr2 = pRow[gy*5+2],
                      pr3 = pRow[gy*5+3], pr4 = pRow[gy*5+4];
                rcur[0] = wx0*pr0;
                rcur[1] = fmaf(wx0, pr1, wx1*pr0);
                rcur[2] = fmaf(wx0, pr2, wx1*pr1);
                rcur[3] = fmaf(wx0, pr3, wx1*pr2);
                rcur[4] = fmaf(wx0, pr4, wx1*pr3);
                rcur[5] = wx1*pr4;
            } else {
                #pragma unroll
                for (int gx = 0; gx < 6; gx++) rcur[gx] = 0.f;
            }
            int iy = iy_base + gy;
            float okY = ((unsigned)iy < (unsigned)H) ? 1.f : 0.f;
            int iyc = min(max(iy, 0), H-1);
            const size_t rowOff = batchOff + (size_t)iyc*WW;
            __half2 rc0 = hz, rc1 = hz, rc2 = hz, rc3 = hz;
            #pragma unroll
            for (int gx = 0; gx < 6; gx++) {
                float coef = wy0 * rcur[gx];
                if (gy > 0) coef = fmaf(wy1, rprev[gx], coef);
                coef *= okY * okX[gx];
                __half2 c2 = __float2half2_rn(coef);
                uint4 vh = __ldg(&vp[(rowOff + ixc[gx])*8 + l]);
                rc0 = __hfma2(c2, *reinterpret_cast<__half2*>(&vh.x), rc0);
                rc1 = __hfma2(c2, *reinterpret_cast<__half2*>(&vh.y), rc1);
                rc2 = __hfma2(c2, *reinterpret_cast<__half2*>(&vh.z), rc2);
                rc3 = __hfma2(c2, *reinterpret_cast<__half2*>(&vh.w), rc3);
            }
            float2 f;
            f = __half22float2(rc0); a0 += f.x; a1 += f.y;
            f = __half22float2(rc1); a2 += f.x; a3 += f.y;
            f = __half22float2(rc2); a4 += f.x; a5 += f.y;
            f = __half22float2(rc3); a6 += f.x; a7 += f.y;
            #pragma unroll
            for (int gx = 0; gx < 6; gx++) rprev[gx] = rcur[gx];
        }
    }

    // Stage mid = acc*inv into smem as fp16 hi + lo residual (8 channels).
    {
        float m[8] = {a0*inv, a1*inv, a2*inv, a3*inv,
                      a4*inv, a5*inv, a6*inv, a7*inv};
        #pragma unroll
        for (int g = 0; g < 4; g++) {
            __half2 h = __floats2half2_rn(m[2*g], m[2*g+1]);
            float2 f = __half22float2(h);
            *(__half2*)&Ah[lp*72 + l*8 + 2*g] = h;
            *(__half2*)&Al[lp*72 + l*8 + 2*g] =
                __floats2half2_rn(m[2*g] - f.x, m[2*g+1] - f.y);
        }
    }

    __syncthreads();

    // ---- Fused 1x1 conv epilogue: 2 compensated m16n8k64 strips per warp ----
    {
        const int r_ = lane >> 2;
        const int qd = lane & 3;
        const int n  = warp*8 + r_;
        const int c0 = warp*8 + qd*2;
        const int xA = x0 + r_;
        #pragma unroll
        for (int s = 0; s < 2; s++) {
            float dfr[4] = {0.f, 0.f, 0.f, 0.f};
            const int rowA = s*16 + r_;
            #pragma unroll
            for (int ks = 0; ks < 4; ks++) {
                const int k0 = ks*16 + qd*2;
                unsigned ah0 = *(const unsigned*)&Ah[ rowA     *72 + k0];
                unsigned ah1 = *(const unsigned*)&Ah[(rowA + 8)*72 + k0];
                unsigned ah2 = *(const unsigned*)&Ah[ rowA     *72 + k0 + 8];
                unsigned ah3 = *(const unsigned*)&Ah[(rowA + 8)*72 + k0 + 8];
                unsigned al0 = *(const unsigned*)&Al[ rowA     *72 + k0];
                unsigned al1 = *(const unsigned*)&Al[(rowA + 8)*72 + k0];
                unsigned al2 = *(const unsigned*)&Al[ rowA     *72 + k0 + 8];
                unsigned al3 = *(const unsigned*)&Al[(rowA + 8)*72 + k0 + 8];
                unsigned bh0 = *(const unsigned*)&Wh[n*72 + k0];
                unsigned bh1 = *(const unsigned*)&Wh[n*72 + k0 + 8];
                unsigned bl0 = *(const unsigned*)&Wl[n*72 + k0];
                unsigned bl1 = *(const unsigned*)&Wl[n*72 + k0 + 8];
                mma16816(dfr, ah0, ah1, ah2, ah3, bh0, bh1);
                mma16816(dfr, al0, al1, al2, al3, bh0, bh1);
                mma16816(dfr, ah0, ah1, ah2, ah3, bl0, bl1);
            }
            out[(size_t)(b*C + c0    )*HW + (y0 + s*2    )*WW + xA] = dfr[0];
            out[(size_t)(b*C + c0 + 1)*HW + (y0 + s*2    )*WW + xA] = dfr[1];
            out[(size_t)(b*C + c0    )*HW + (y0 + s*2 + 1)*WW + xA] = dfr[2];
            out[(size_t)(b*C + c0 + 1)*HW + (y0 + s*2 + 1)*WW + xA] = dfr[3];
        }
    }

    // attn map [n, nh, k2, h, w]; 4*25*32 = 3200 values per block.
    for (int i = tid; i < NH*K2*32; i += 256) {
        int pi = i & 31;
        int ht = i >> 5;
        int hh = ht / K2, t = ht % K2;
        float val = sP[pi][hh][t] * sInv[pi][hh];
        int py = y0 + (pi >> 3);
        int px = x0 + (pi & 7);
        attn_out[((size_t)(b*NH + hh)*K2 + t)*HW + py*WW + px] = val;
    }
}

// ---------------------------------------------------------------------------
extern "C" void kernel_launch(void* const* d_in, const int* in_sizes, int n_in,
                              void* d_out, int out_size)
{
    const float* q    = (const float*)d_in[0];
    const float* k    = (const float*)d_in[1];
    const float* v    = (const float*)d_in[2];
    const float* flow = (const float*)d_in[3];
    const float* Wq   = (const float*)d_in[4];
    const float* Wk   = (const float*)d_in[5];
    const float* Wv   = (const float*)d_in[6];
    const float* Wfc  = (const float*)d_in[7];

    float* out  = (float*)d_out;              // [n, c, h, w]
    float* attn = out + NB*C*HW;              // [n, nh, k2, h, w]

    dim3 g1(NB*HW/128, 3);
    conv_in_kernel<<<g1, 256>>>(q, k, v, Wq, Wk, Wv);
    attn_kernel<<<NB*16*32, 256>>>(flow, Wfc, out, attn);   // 8x4 tiles, fused
}

// round 17
// speedup vs baseline: 1.2163x; 1.1004x over previous
#include <cuda_runtime.h>
#include <cuda_fp16.h>

#define NB   2
#define C    64
#define H    128
#define WW   128
#define HW   (H*WW)
#define NH   4
#define DK   16
#define KS   5
#define K2   25

// Scratch (allocation-free rule: __device__ globals).
// qp/kp/vp stored as fp16, pixel-major: [n, h*w, c].
__device__ uint2 g_qp [NB*HW*16];
__device__ uint2 g_kp [NB*HW*16];
__device__ uint2 g_vp [NB*HW*16];
// Pre-converted Wfc (hi + residual lo), dense [out][c].
__device__ __half g_Wfch[64*64];
__device__ __half g_Wfcl[64*64];

__device__ __forceinline__ float ex2f(float x) {
    float r;
    asm("ex2.approx.f32 %0, %1;" : "=f"(r) : "f"(x));
    return r;
}

__device__ __forceinline__ void mma16816(float d[4],
    unsigned a0, unsigned a1, unsigned a2, unsigned a3,
    unsigned b0, unsigned b1)
{
    asm volatile(
        "mma.sync.aligned.m16n8k16.row.col.f32.f16.f16.f32 "
        "{%0,%1,%2,%3}, {%4,%5,%6,%7}, {%8,%9}, {%0,%1,%2,%3};"
        : "+f"(d[0]), "+f"(d[1]), "+f"(d[2]), "+f"(d[3])
        : "r"(a0), "r"(a1), "r"(a2), "r"(a3), "r"(b0), "r"(b1));
}

// ---------------------------------------------------------------------------
// Kernel 1: three 1x1 convs via tensor cores; smem-bounced coalesced output.
// Block (which==0, bx==0) additionally pre-converts Wfc to fp16 hi/lo.
// ---------------------------------------------------------------------------
__global__ __launch_bounds__(256) void conv_in_kernel(
    const float* __restrict__ q,
    const float* __restrict__ k,
    const float* __restrict__ v,
    const float* __restrict__ Wq,
    const float* __restrict__ Wk,
    const float* __restrict__ Wv,
    const float* __restrict__ Wfc)
{
    __shared__ __half Xh[128*72];   // [pix][c], stride 72 halves; reused for D
    __shared__ __half Wh[64*72];    // [out][c], stride 72 halves

    const int which = blockIdx.y;
    const float* src = (which == 0) ? q  : (which == 1) ? k  : v;
    const float* Wsrc= (which == 0) ? Wq : (which == 1) ? Wk : Wv;
    uint2*       dst = (which == 0) ? g_qp : (which == 1) ? g_kp : g_vp;

    const int b       = blockIdx.x / (HW/128);
    const int pixBase = (blockIdx.x % (HW/128)) * 128;
    const int tid     = threadIdx.x;

    // One block pre-converts Wfc -> g_Wfch/g_Wfcl (no dependency on anything).
    if (which == 0 && blockIdx.x == 0) {
        for (int i = tid; i < 64*16; i += 256) {
            int o = i >> 4, c4 = (i & 15)*4;
            float4 w = __ldg((const float4*)(Wfc + o*64 + c4));
            __half2 hh0 = __floats2half2_rn(w.x, w.y);
            __half2 hh1 = __floats2half2_rn(w.z, w.w);
            float2 r0 = __half22float2(hh0);
            float2 r1 = __half22float2(hh1);
            *(__half2*)&g_Wfch[o*64 + c4]     = hh0;
            *(__half2*)&g_Wfch[o*64 + c4 + 2] = hh1;
            *(__half2*)&g_Wfcl[o*64 + c4]     = __floats2half2_rn(w.x - r0.x, w.y - r0.y);
            *(__half2*)&g_Wfcl[o*64 + c4 + 2] = __floats2half2_rn(w.z - r1.x, w.w - r1.y);
        }
    }

    {
        const int pixL = tid & 127;
        const int cg   = tid >> 7;          // 0 or 1
        #pragma unroll
        for (int g = 0; g < 8; g++) {
            int c = g*8 + cg*4;
            const float* s = src + (size_t)(b*C + c)*HW + pixBase + pixL;
            float x0 = __ldg(s);
            float x1 = __ldg(s + HW);
            float x2 = __ldg(s + 2*HW);
            float x3 = __ldg(s + 3*HW);
            *(__half2*)&Xh[pixL*72 + c]     = __floats2half2_rn(x0, x1);
            *(__half2*)&Xh[pixL*72 + c + 2] = __floats2half2_rn(x2, x3);
        }
    }
    for (int i = tid; i < 64*16; i += 256) {
        int out = i >> 4, c4 = (i & 15)*4;
        float4 w = __ldg((const float4*)(Wsrc + out*64 + c4));
        *(__half2*)&Wh[out*72 + c4]     = __floats2half2_rn(w.x, w.y);
        *(__half2*)&Wh[out*72 + c4 + 2] = __floats2half2_rn(w.z, w.w);
    }
    __syncthreads();

    const int warp = tid >> 5;
    const int lane = tid & 31;
    const int r  = lane >> 2;
    const int qd = lane & 3;

    float d[8][4];
    #pragma unroll
    for (int nt = 0; nt < 8; nt++)
        #pragma unroll
        for (int i = 0; i < 4; i++) d[nt][i] = 0.f;

    const int rowA = warp*16 + r;
    #pragma unroll
    for (int ks = 0; ks < 4; ks++) {
        const int k0 = ks*16 + qd*2;
        unsigned a0 = *(const unsigned*)&Xh[ rowA      *72 + k0];
        unsigned a1 = *(const unsigned*)&Xh[(rowA + 8) *72 + k0];
        unsigned a2 = *(const unsigned*)&Xh[ rowA      *72 + k0 + 8];
        unsigned a3 = *(const unsigned*)&Xh[(rowA + 8) *72 + k0 + 8];
        #pragma unroll
        for (int nt = 0; nt < 8; nt++) {
            const int n = nt*8 + r;
            unsigned b0 = *(const unsigned*)&Wh[n*72 + k0];
            unsigned b1 = *(const unsigned*)&Wh[n*72 + k0 + 8];
            mma16816(d[nt], a0, a1, a2, a3, b0, b1);
        }
    }

    // Reuse Xh as fp16 D staging buffer, then fully-coalesced STG.128 out.
    __syncthreads();
    #pragma unroll
    for (int nt = 0; nt < 8; nt++) {
        const int cHalf = nt*8 + qd*2;
        const int pixLa = warp*16 + r;
        *(__half2*)&Xh[ pixLa     *72 + cHalf] = __floats2half2_rn(d[nt][0], d[nt][1]);
        *(__half2*)&Xh[(pixLa + 8)*72 + cHalf] = __floats2half2_rn(d[nt][2], d[nt][3]);
    }
    __syncthreads();

    uint4* dst4 = (uint4*)dst;
    #pragma unroll
    for (int kk = 0; kk < 4; kk++) {
        int u = tid + kk*256;
        int pixL = u >> 3;
        int oct  = u & 7;
        uint4 val = *(const uint4*)&Xh[pixL*72 + oct*8];
        dst4[(size_t)(b*HW + pixBase + pixL)*8 + oct] = val;
    }
}

// ---------------------------------------------------------------------------
// Kernel 2: flow-guided attention + fused final 1x1 conv.
// Four pixels/warp (lane owns 8 channels, LDG.128 gathers). Probs normalized
// in pass A and published to sP (no sInv). Wfc hi/lo copied pre-converted from
// global (no per-block converts). Epilogue: Ah*(Wh+Wl) compensated MMA (mid
// residual dropped; ~2.4e-4 add'l error). Vectorized attn-map writeout.
// ---------------------------------------------------------------------------
__global__ __launch_bounds__(256, 3) void attn_kernel(const float* __restrict__ flow,
                                                      float* __restrict__ out,
                                                      float* __restrict__ attn_out)
{
    __shared__ float sP[32][NH][K2];
    __shared__ __half Ah[32*72];    // mid fp16 [pix][c]
    __shared__ __half Wh[64*72];    // Wfc hi [out][c]
    __shared__ __half Wl[64*72];    // Wfc lo

    const int tid  = threadIdx.x;
    const int warp = tid >> 5;
    const int lane = tid & 31;
    const int sp   = lane >> 3;      // subpixel 0..3
    const int l    = lane & 7;       // channel group: channels 8l..8l+7

    // Tile: 8 wide x 4 tall. 16 x-tiles, 32 y-tiles, NB batches.
    const int bx = blockIdx.x & 15;
    const int by = (blockIdx.x >> 4) & 31;
    const int b  = blockIdx.x >> 9;
    const int x0 = bx * 8;
    const int y0 = by * 4;

    const int lp = warp*4 + sp;      // local pixel 0..31
    const int rx = lp & 7;
    const int ry = lp >> 3;
    const int x = x0 + rx;
    const int y = y0 + ry;
    const int pix = y*WW + x;

    // Stage Wfc hi/lo: straight uint4 copies of pre-converted fp16.
    for (int i = tid; i < 512; i += 256) {
        int o = i >> 3, oct = i & 7;
        *(uint4*)&Wh[o*72 + oct*8] = *(const uint4*)&g_Wfch[o*64 + oct*8];
        *(uint4*)&Wl[o*72 + oct*8] = *(const uint4*)&g_Wfcl[o*64 + oct*8];
    }

    const float fx = flow[(b*2 + 0)*HW + pix];
    const float fy = flow[(b*2 + 1)*HW + pix];

    const float axf = (float)x + fx;
    const float ayf = (float)y + fy;
    const float x0f = floorf(axf), y0f = floorf(ayf);
    const int ix_base = (int)x0f - 2;
    const int iy_base = (int)y0f - 2;
    const float wx1 = axf - x0f, wx0 = 1.f - wx1;
    const float wy1 = ayf - y0f, wy0 = 1.f - wy1;
    const float LOG2E = 1.4426950408889634f;
    const float wy0e = wy0 * LOG2E, wy1e = wy1 * LOG2E;

    const uint4* __restrict__ qp = (const uint4*)g_qp;
    const uint4* __restrict__ kp = (const uint4*)g_kp;
    const uint4* __restrict__ vp = (const uint4*)g_vp;

    // q: 8 channels per lane, pre-scaled by 0.25 (exact in fp16).
    uint4 qh = __ldg(&qp[(size_t)(b*HW + pix)*8 + l]);
    const __half2 sc = __float2half2_rn(0.25f);
    const __half2 q01 = __hmul2(*reinterpret_cast<__half2*>(&qh.x), sc);
    const __half2 q23 = __hmul2(*reinterpret_cast<__half2*>(&qh.y), sc);
    const __half2 q45 = __hmul2(*reinterpret_cast<__half2*>(&qh.z), sc);
    const __half2 q67 = __hmul2(*reinterpret_cast<__half2*>(&qh.w), sc);

    const size_t batchOff = (size_t)b*HW;

    const bool interior = (ix_base >= 0) & (ix_base <= WW-6) &
                          (iy_base >= 0) & (iy_base <= H-6);
    const bool fastPath = __all_sync(0xffffffffu, interior);

    const int head = l >> 1;

    // ---- Pass A: per-lane PARTIAL logits (8-channel dots, reduction deferred) ----
    {
        float p[25];
        float drow[2][6];

        if (fastPath) {
            const uint4* kbase = kp + (batchOff + (size_t)iy_base*WW + ix_base)*8 + l;
            #pragma unroll
            for (int dy = 0; dy < 6; dy++) {
                const int cur = dy & 1;
                const uint4* kr = kbase + dy*(WW*8);
                #pragma unroll
                for (int dx = 0; dx < 6; dx++) {
                    uint4 kh = __ldg(kr + dx*8);
                    __half2 t = __hfma2(q01, *reinterpret_cast<__half2*>(&kh.x),
                                __hfma2(q23, *reinterpret_cast<__half2*>(&kh.y),
                                __hfma2(q45, *reinterpret_cast<__half2*>(&kh.z),
                                __hmul2(q67, *reinterpret_cast<__half2*>(&kh.w)))));
                    float2 tf = __half22float2(t);
                    drow[cur][dx] = tf.x + tf.y;
                }
                if (dy > 0) {
                    const int prv = cur ^ 1;
                    #pragma unroll
                    for (int tx = 0; tx < 5; tx++)
                        p[(dy-1)*5 + tx] =
                              wy0e * fmaf(wx0, drow[prv][tx], wx1 * drow[prv][tx+1])
                            + wy1e * fmaf(wx0, drow[cur][tx], wx1 * drow[cur][tx+1]);
                }
            }
        } else {
            int   ixc[6];
            float okX[6];
            #pragma unroll
            for (int dx = 0; dx < 6; dx++) {
                int ix = ix_base + dx;
                okX[dx] = ((unsigned)ix < (unsigned)WW) ? 1.f : 0.f;
                ixc[dx] = min(max(ix, 0), WW-1);
            }
            #pragma unroll
            for (int dy = 0; dy < 6; dy++) {
                const int cur = dy & 1;
                int iy = iy_base + dy;
                float okY = ((unsigned)iy < (unsigned)H) ? 1.f : 0.f;
                int iyc = min(max(iy, 0), H-1);
                const size_t rowOff = batchOff + (size_t)iyc*WW;
                #pragma unroll
                for (int dx = 0; dx < 6; dx++) {
                    uint4 kh = __ldg(&kp[(rowOff + ixc[dx])*8 + l]);
                    __half2 t = __hfma2(q01, *reinterpret_cast<__half2*>(&kh.x),
                                __hfma2(q23, *reinterpret_cast<__half2*>(&kh.y),
                                __hfma2(q45, *reinterpret_cast<__half2*>(&kh.z),
                                __hmul2(q67, *reinterpret_cast<__half2*>(&kh.w)))));
                    float2 tf = __half22float2(t);
                    drow[cur][dx] = (tf.x + tf.y) * (okY * okX[dx]);
                }
                if (dy > 0) {
                    const int prv = cur ^ 1;
                    #pragma unroll
                    for (int tx = 0; tx < 5; tx++)
                        p[(dy-1)*5 + tx] =
                              wy0e * fmaf(wx0, drow[prv][tx], wx1 * drow[prv][tx+1])
                            + wy1e * fmaf(wx0, drow[cur][tx], wx1 * drow[cur][tx+1]);
                }
            }
        }

        // Deferred head reduction: lane pair (l, l^1) spans one head's 16 ch.
        #pragma unroll
        for (int t = 0; t < K2; t++)
            p[t] += __shfl_xor_sync(0xffffffffu, p[t], 1);

        // Softmax (log2 domain, no max-shift). Publish NORMALIZED probs.
        float sum = 0.f;
        #pragma unroll
        for (int t = 0; t < K2; t++) { p[t] = ex2f(p[t]); sum += p[t]; }

        if ((lane & 1) == 0) {
            const float nv = 1.f / sum;
            #pragma unroll
            for (int t = 0; t < K2; t++) sP[lp][head][t] = p[t] * nv;
        }
    }
    __syncwarp();

    const float* __restrict__ pRow = &sP[lp][head][0];

    // ---- Pass B: V accumulation; fp16 row accumulators, fp32 row flush ----
    float a0 = 0.f, a1 = 0.f, a2 = 0.f, a3 = 0.f,
          a4 = 0.f, a5 = 0.f, a6 = 0.f, a7 = 0.f;
    float rprev[6], rcur[6];
    const __half2 hz = __float2half2_rn(0.f);

    if (fastPath) {
        const uint4* vbase = vp + (batchOff + (size_t)iy_base*WW + ix_base)*8 + l;
        #pragma unroll
        for (int gy = 0; gy < 6; gy++) {
            if (gy < 5) {
                float pr0 = pRow[gy*5+0], pr1 = pRow[gy*5+1], pr2 = pRow[gy*5+2],
                      pr3 = pRow[gy*5+3], pr4 = pRow[gy*5+4];
                rcur[0] = wx0*pr0;
                rcur[1] = fmaf(wx0, pr1, wx1*pr0);
                rcur[2] = fmaf(wx0, pr2, wx1*pr1);
                rcur[3] = fmaf(wx0, pr3, wx1*pr2);
                rcur[4] = fmaf(wx0, pr4, wx1*pr3);
                rcur[5] = wx1*pr4;
            } else {
                #pragma unroll
                for (int gx = 0; gx < 6; gx++) rcur[gx] = 0.f;
            }
            const uint4* vr = vbase + gy*(WW*8);
            __half2 rc0 = hz, rc1 = hz, rc2 = hz, rc3 = hz;
            #pragma unroll
            for (int gx = 0; gx < 6; gx++) {
                float coef = wy0 * rcur[gx];
                if (gy > 0) coef = fmaf(wy1, rprev[gx], coef);
                __half2 c2 = __float2half2_rn(coef);
                uint4 vh = __ldg(vr + gx*8);
                rc0 = __hfma2(c2, *reinterpret_cast<__half2*>(&vh.x), rc0);
                rc1 = __hfma2(c2, *reinterpret_cast<__half2*>(&vh.y), rc1);
                rc2 = __hfma2(c2, *reinterpret_cast<__half2*>(&vh.z), rc2);
                rc3 = __hfma2(c2, *reinterpret_cast<__half2*>(&vh.w), rc3);
            }
            float2 f;
            f = __half22float2(rc0); a0 += f.x; a1 += f.y;
            f = __half22float2(rc1); a2 += f.x; a3 += f.y;
            f = __half22float2(rc2); a4 += f.x; a5 += f.y;
            f = __half22float2(rc3); a6 += f.x; a7 += f.y;
            #pragma unroll
            for (int gx = 0; gx < 6; gx++) rprev[gx] = rcur[gx];
        }
    } else {
        int   ixc[6];
        float okX[6];
        #pragma unroll
        for (int dx = 0; dx < 6; dx++) {
            int ix = ix_base + dx;
            okX[dx] = ((unsigned)ix < (unsigned)WW) ? 1.f : 0.f;
            ixc[dx] = min(max(ix, 0), WW-1);
        }
        #pragma unroll
        for (int gy = 0; gy < 6; gy++) {
            if (gy < 5) {
                float pr0 = pRow[gy*5+0], pr1 = pRow[gy*5+1], pr2 = pRow[gy*5+2],
                      pr3 = pRow[gy*5+3], pr4 = pRow[gy*5+4];
                rcur[0] = wx0*pr0;
                rcur[1] = fmaf(wx0, pr1, wx1*pr0);
                rcur[2] = fmaf(wx0, pr2, wx1*pr1);
                rcur[3] = fmaf(wx0, pr3, wx1*pr2);
                rcur[4] = fmaf(wx0, pr4, wx1*pr3);
                rcur[5] = wx1*pr4;
            } else {
                #pragma unroll
                for (int gx = 0; gx < 6; gx++) rcur[gx] = 0.f;
            }
            int iy = iy_base + gy;
            float okY = ((unsigned)iy < (unsigned)H) ? 1.f : 0.f;
            int iyc = min(max(iy, 0), H-1);
            const size_t rowOff = batchOff + (size_t)iyc*WW;
            __half2 rc0 = hz, rc1 = hz, rc2 = hz, rc3 = hz;
            #pragma unroll
            for (int gx = 0; gx < 6; gx++) {
                float coef = wy0 * rcur[gx];
                if (gy > 0) coef = fmaf(wy1, rprev[gx], coef);
                coef *= okY * okX[gx];
                __half2 c2 = __float2half2_rn(coef);
                uint4 vh = __ldg(&vp[(rowOff + ixc[gx])*8 + l]);
                rc0 = __hfma2(c2, *reinterpret_cast<__half2*>(&vh.x), rc0);
                rc1 = __hfma2(c2, *reinterpret_cast<__half2*>(&vh.y), rc1);
                rc2 = __hfma2(c2, *reinterpret_cast<__half2*>(&vh.z), rc2);
                rc3 = __hfma2(c2, *reinterpret_cast<__half2*>(&vh.w), rc3);
            }
            float2 f;
            f = __half22float2(rc0); a0 += f.x; a1 += f.y;
            f = __half22float2(rc1); a2 += f.x; a3 += f.y;
            f = __half22float2(rc2); a4 += f.x; a5 += f.y;
            f = __half22float2(rc3); a6 += f.x; a7 += f.y;
            #pragma unroll
            for (int gx = 0; gx < 6; gx++) rprev[gx] = rcur[gx];
        }
    }

    // Stage mid into smem as fp16 (probs already normalized -> acc is mid).
    #pragma unroll
    for (int g = 0; g < 4; g++) {
        float m0 = (g == 0) ? a0 : (g == 1) ? a2 : (g == 2) ? a4 : a6;
        float m1 = (g == 0) ? a1 : (g == 1) ? a3 : (g == 2) ? a5 : a7;
        *(__half2*)&Ah[lp*72 + l*8 + 2*g] = __floats2half2_rn(m0, m1);
    }

    __syncthreads();

    // ---- Fused 1x1 conv epilogue: compensated Ah*(Wh+Wl), 2 strips/warp ----
    {
        const int r_ = lane >> 2;
        const int qd = lane & 3;
        const int n  = warp*8 + r_;
        const int c0 = warp*8 + qd*2;
        const int xA = x0 + r_;
        #pragma unroll
        for (int s = 0; s < 2; s++) {
            float dfr[4] = {0.f, 0.f, 0.f, 0.f};
            const int rowA = s*16 + r_;
            #pragma unroll
            for (int ks = 0; ks < 4; ks++) {
                const int k0 = ks*16 + qd*2;
                unsigned ah0 = *(const unsigned*)&Ah[ rowA     *72 + k0];
                unsigned ah1 = *(const unsigned*)&Ah[(rowA + 8)*72 + k0];
                unsigned ah2 = *(const unsigned*)&Ah[ rowA     *72 + k0 + 8];
                unsigned ah3 = *(const unsigned*)&Ah[(rowA + 8)*72 + k0 + 8];
                unsigned bh0 = *(const unsigned*)&Wh[n*72 + k0];
                unsigned bh1 = *(const unsigned*)&Wh[n*72 + k0 + 8];
                unsigned bl0 = *(const unsigned*)&Wl[n*72 + k0];
                unsigned bl1 = *(const unsigned*)&Wl[n*72 + k0 + 8];
                mma16816(dfr, ah0, ah1, ah2, ah3, bh0, bh1);
                mma16816(dfr, ah0, ah1, ah2, ah3, bl0, bl1);
            }
            out[(size_t)(b*C + c0    )*HW + (y0 + s*2    )*WW + xA] = dfr[0];
            out[(size_t)(b*C + c0 + 1)*HW + (y0 + s*2    )*WW + xA] = dfr[1];
            out[(size_t)(b*C + c0    )*HW + (y0 + s*2 + 1)*WW + xA] = dfr[2];
            out[(size_t)(b*C + c0 + 1)*HW + (y0 + s*2 + 1)*WW + xA] = dfr[3];
        }
    }

    // attn map [n, nh, k2, h, w]; vectorized: thread owns 4-px group (pg),
    // strides over (head,tap). px = x0 + (pg&1)*4, py = y0 + (pg>>1).
    {
        const int pg = tid & 7;
        const int py = y0 + (pg >> 1);
        const int px = x0 + (pg & 1)*4;
        const int pibase = pg*4;
        for (int ht = tid >> 3; ht < NH*K2; ht += 32) {
            int hh = ht / K2;
            int t  = ht - hh*K2;
            float4 vv;
            vv.x = sP[pibase+0][hh][t];
            vv.y = sP[pibase+1][hh][t];
            vv.z = sP[pibase+2][hh][t];
            vv.w = sP[pibase+3][hh][t];
            *(float4*)&attn_out[((size_t)(b*NH + hh)*K2 + t)*HW + py*WW + px] = vv;
        }
    }
}

// ---------------------------------------------------------------------------
extern "C" void kernel_launch(void* const* d_in, const int* in_sizes, int n_in,
                              void* d_out, int out_size)
{
    const float* q    = (const float*)d_in[0];
    const float* k    = (const float*)d_in[1];
    const float* v    = (const float*)d_in[2];
    const float* flow = (const float*)d_in[3];
    const float* Wq   = (const float*)d_in[4];
    const float* Wk   = (const float*)d_in[5];
    const float* Wv   = (const float*)d_in[6];
    const float* Wfc  = (const float*)d_in[7];

    float* out  = (float*)d_out;              // [n, c, h, w]
    float* attn = out + NB*C*HW;              // [n, nh, k2, h, w]

    dim3 g1(NB*HW/128, 3);
    conv_in_kernel<<<g1, 256>>>(q, k, v, Wq, Wk, Wv, Wfc);
    attn_kernel<<<NB*16*32, 256>>>(flow, out, attn);   // 8x4 tiles, fused
}